// round 16
// baseline (speedup 1.0000x reference)
#include <cuda_runtime.h>
#include <cuda_fp16.h>
#include <cstdint>

#define B_   8
#define N_   2048
#define DIN  256
#define HID  64
#define TI   128
#define CH   32
#define NCH  (N_ / CH)        // 64
#define L2E  1.4426950408889634f

// ---- gat_main dynamic SMEM: 3 groups x 3-slot rings ----
#define SLOT_A  (128 * 144)                 // adj tile: 128 rows x 32 ints, 144B-padded
#define ABYTES  (9 * SLOT_A)                // 3 groups x 3 slots = 165888
#define SLOT_B  (32 * 144)                  // B tile: 32 nodes x 64 fp16
#define BOFF    ABYTES
#define BBYTES  (9 * SLOT_B)                // 41472
#define F2EOFF  (BOFF + BBYTES)             // 207360
#define SMEM_DYN (F2EOFF + N_ * 4)          // 215552

// ---- gemm_wh dynamic SMEM (R12-proven) ----
#define GW_WOFF  0                          // W fp16 [256][72]  = 36864
#define GW_XOFF  36864                      // X ring: 4 slots x (128 x 144B)
#define GW_XSLOT 18432
#define SMEM_GW  (GW_XOFF + 4 * GW_XSLOT)   // 110592

// Scratch (device globals — no allocation allowed)
__device__ uint32_t g_Whh[B_ * N_ * HID / 2];       // fp16x2 Wh  [node][h/2]
__device__ float g_f1e[B_ * N_];                    // f1*log2e
__device__ float g_f2e[B_ * N_];                    // f2*log2e

// ---------------- helpers ----------------
static __device__ __forceinline__ uint32_t smem_u32(const void* p) {
    uint32_t a;
    asm("{ .reg .u64 t; cvta.to.shared.u64 t, %1; cvt.u32.u64 %0, t; }"
        : "=r"(a) : "l"(p));
    return a;
}
static __device__ __forceinline__ float ex2(float x) {
    float y;
    asm("ex2.approx.f32 %0, %1;" : "=f"(y) : "f"(x));
    return y;
}
static __device__ __forceinline__ uint32_t pack2h(float w0, float w1) {
    uint32_t r;
    asm("cvt.rn.f16x2.f32 %0, %1, %2;" : "=r"(r) : "f"(w1), "f"(w0));
    return r;
}
// split pair into fp16 hi + fp16 lo (exact residual, ~2^-22 rel)
static __device__ __forceinline__ void split2h(float w0, float w1,
                                               uint32_t& hi, uint32_t& lo) {
    uint32_t h = pack2h(w0, w1);
    float h0, h1;
    asm("{ .reg .f16 a,b; mov.b32 {a,b}, %2; cvt.f32.f16 %0, a; cvt.f32.f16 %1, b; }"
        : "=f"(h0), "=f"(h1) : "r"(h));
    lo = pack2h(w0 - h0, w1 - h1);
    hi = h;
}
static __device__ __forceinline__ void ldsm4t(uint32_t& r0, uint32_t& r1,
                                              uint32_t& r2, uint32_t& r3,
                                              uint32_t a) {
    asm volatile("ldmatrix.sync.aligned.m8n8.x4.trans.shared.b16 {%0,%1,%2,%3}, [%4];"
                 : "=r"(r0), "=r"(r1), "=r"(r2), "=r"(r3) : "r"(a));
}
static __device__ __forceinline__ void lds64(int2& v, uint32_t a) {
    asm volatile("ld.shared.v2.u32 {%0,%1}, [%2];" : "=r"(v.x), "=r"(v.y) : "r"(a));
}
static __device__ __forceinline__ void lds64f(float2& v, uint32_t a) {
    asm volatile("ld.shared.v2.f32 {%0,%1}, [%2];" : "=f"(v.x), "=f"(v.y) : "r"(a));
}
static __device__ __forceinline__ void mma16816(float* c, const uint32_t* a,
                                                uint32_t b0, uint32_t b1) {
    asm volatile(
        "mma.sync.aligned.m16n8k16.row.col.f32.f16.f16.f32 "
        "{%0,%1,%2,%3}, {%4,%5,%6,%7}, {%8,%9}, {%0,%1,%2,%3};"
        : "+f"(c[0]), "+f"(c[1]), "+f"(c[2]), "+f"(c[3])
        : "r"(a[0]), "r"(a[1]), "r"(a[2]), "r"(a[3]), "r"(b0), "r"(b1));
}
#define CP_ASYNC16(dst, src) \
    asm volatile("cp.async.cg.shared.global [%0], [%1], 16;" :: "r"(dst), "l"(src) : "memory")
#define CP_COMMIT()  asm volatile("cp.async.commit_group;" ::: "memory")
#define CP_WAIT1()   asm volatile("cp.async.wait_group 1;" ::: "memory")
#define CP_WAIT2()   asm volatile("cp.async.wait_group 2;" ::: "memory")
#define CP_WAIT0()   asm volatile("cp.async.wait_group 0;" ::: "memory")
#define GBAR(id)     asm volatile("bar.sync %0, 256;" :: "r"(id) : "memory")

// ---------------------------------------------------------------------------
// Kernel A (R12-proven, unchanged): Wh = X @ W via mma.sync fp16 2-term split;
// emits packed fp16x2 Wh and per-node f1/f2 exponent factors.
// ---------------------------------------------------------------------------
__global__ __launch_bounds__(256) void gemm_wh(const float* __restrict__ X,
                                               const float* __restrict__ W,
                                               const float* __restrict__ a) {
    extern __shared__ __align__(16) char smw[];
    const uint32_t smb = smem_u32(smw);
    const uint32_t wsb = smb + GW_WOFF;
    const uint32_t xsb = smb + GW_XOFF;

    const int tid = threadIdx.x;
    const int lane = tid & 31, w8 = tid >> 5;
    const int g = lane >> 2, tg = lane & 3;
    const int r0 = blockIdx.x * 128;

#pragma unroll
    for (int i = 0; i < 16; i++) {
        const int e = (i * 256 + tid) * 4;
        const int k = e >> 6, n = e & 63;
        const float4 wv = *(const float4*)(W + e);
        *(uint32_t*)(smw + GW_WOFF + k * 144 + n * 2)     = pack2h(wv.x, wv.y);
        *(uint32_t*)(smw + GW_WOFF + k * 144 + n * 2 + 4) = pack2h(wv.z, wv.w);
    }

    const int xrow = tid >> 1;
    const uint32_t xdst = xsb + xrow * 144 + (tid & 1) * 64;
    const float* xsrc = X + (size_t)(r0 + xrow) * DIN + (tid & 1) * 16;

#pragma unroll
    for (int p = 0; p < 3; p++) {
#pragma unroll
        for (int q = 0; q < 4; q++)
            CP_ASYNC16(xdst + p * GW_XSLOT + q * 16, xsrc + p * 32 + q * 4);
        CP_COMMIT();
    }

    float c[8][4];
#pragma unroll
    for (int nt = 0; nt < 8; nt++)
#pragma unroll
        for (int q = 0; q < 4; q++) c[nt][q] = 0.f;

    for (int kc = 0; kc < 8; kc++) {
        CP_WAIT2();
        __syncthreads();
        if (kc + 3 < 8) {
#pragma unroll
            for (int q = 0; q < 4; q++)
                CP_ASYNC16(xdst + ((kc + 3) & 3) * GW_XSLOT + q * 16,
                           xsrc + (kc + 3) * 32 + q * 4);
        }
        CP_COMMIT();

        const uint32_t xslot = xsb + (kc & 3) * GW_XSLOT;
#pragma unroll
        for (int s = 0; s < 2; s++) {
            const uint32_t abase = xslot + (w8 * 16 + g) * 144 + (s * 16 + 2 * tg) * 4;
            float2 x0, x1, x2, x3;
            lds64f(x0, abase);
            lds64f(x1, abase + 8 * 144);
            lds64f(x2, abase + 32);
            lds64f(x3, abase + 8 * 144 + 32);
            uint32_t ahi[4], alo[4];
            split2h(x0.x, x0.y, ahi[0], alo[0]);
            split2h(x1.x, x1.y, ahi[1], alo[1]);
            split2h(x2.x, x2.y, ahi[2], alo[2]);
            split2h(x3.x, x3.y, ahi[3], alo[3]);

            const uint32_t brd = wsb + (kc * 32 + s * 16 + (lane & 15)) * 144 +
                                 ((lane >> 4) << 4);
#pragma unroll
            for (int n16 = 0; n16 < 4; n16++) {
                uint32_t b0, b1, b2, b3;
                ldsm4t(b0, b1, b2, b3, brd + n16 * 32);
                mma16816(c[n16 * 2],     ahi, b0, b1);
                mma16816(c[n16 * 2],     alo, b0, b1);
                mma16816(c[n16 * 2 + 1], ahi, b2, b3);
                mma16816(c[n16 * 2 + 1], alo, b2, b3);
            }
        }
    }

    const int r_lo = w8 * 16 + g, r_hi = r_lo + 8;
    float p1lo = 0.f, p2lo = 0.f, p1hi = 0.f, p2hi = 0.f;
#pragma unroll
    for (int nt = 0; nt < 8; nt++) {
        const int col = nt * 8 + 2 * tg;
        const float a1x = a[col], a1y = a[col + 1];
        const float a2x = a[HID + col], a2y = a[HID + col + 1];
        p1lo += c[nt][0] * a1x + c[nt][1] * a1y;
        p2lo += c[nt][0] * a2x + c[nt][1] * a2y;
        p1hi += c[nt][2] * a1x + c[nt][3] * a1y;
        p2hi += c[nt][2] * a2x + c[nt][3] * a2y;
        g_Whh[(size_t)(r0 + r_lo) * 32 + nt * 4 + tg] = pack2h(c[nt][0], c[nt][1]);
        g_Whh[(size_t)(r0 + r_hi) * 32 + nt * 4 + tg] = pack2h(c[nt][2], c[nt][3]);
    }
#pragma unroll
    for (int s = 1; s <= 2; s <<= 1) {
        p1lo += __shfl_xor_sync(0xffffffffu, p1lo, s);
        p2lo += __shfl_xor_sync(0xffffffffu, p2lo, s);
        p1hi += __shfl_xor_sync(0xffffffffu, p1hi, s);
        p2hi += __shfl_xor_sync(0xffffffffu, p2hi, s);
    }
    if (tg == 0) {
        g_f1e[r0 + r_lo] = p1lo * L2E;
        g_f2e[r0 + r_lo] = p2lo * L2E;
        g_f1e[r0 + r_hi] = p1hi * L2E;
        g_f2e[r0 + r_hi] = p2hi * L2E;
    }
}

// ---------------------------------------------------------------------------
// Main kernel: R12 loop body VERBATIM, but THREE 8-warp groups (768 threads):
// group g handles chunks ch ≡ g (mod 3) with a private 3-slot ring
// (depth-2 prefetch, commit-per-chunk, wait_group(1), GBAR per chunk).
// 6 warps/SMSP in 3 independent barrier domains. 3-way merge at the end.
// ---------------------------------------------------------------------------
__global__ __launch_bounds__(768) void gat_main(const int* __restrict__ adj,
                                                float* __restrict__ out) {
    extern __shared__ __align__(16) char sm[];
    const uint32_t smb = smem_u32(sm);
    float* f2e_s = (float*)(sm + F2EOFF);

    const int tid = threadIdx.x;
    const int wg = tid >> 8;                 // warpgroup 0/1/2 (chunk mod 3)
    const int wtid = tid & 255;
    const int lane = tid & 31, w8 = wtid >> 5;   // warp-in-group 0..7
    const int g = lane >> 2, tg = lane & 3;
    const int b = blockIdx.x >> 4;
    const int i0 = (blockIdx.x & 15) * TI;
    const int base = b * N_;

    const int r_lo = w8 * 16 + g, r_hi = r_lo + 8;
    const int glen = (wg == 0) ? 22 : 21;    // chunks for this group (3k+wg < 64)

    const int* adjb = adj + (size_t)b * N_ * N_ + (size_t)i0 * N_;
    const uint32_t* whh = g_Whh + (size_t)base * 32;

    // group-private ring bases (3 slots each)
    const uint32_t agb = smb + wg * 3 * SLOT_A;
    const uint32_t bgb = smb + BOFF + wg * 3 * SLOT_B;

    // cp.async segment mapping (within group) — R12 mapping verbatim
    const int arow = wtid >> 3, acol = (wtid & 7) * 4;
    const uint32_t a_woff = arow * 144 + acol * 4;           // +q*32*144
    const uint32_t b_woff = (wtid >> 3) * 144 + (wtid & 7) * 16;

    // stage f2e table (first 512 threads: one float4 each)
    if (tid < 512) {
        const int idx = tid * 4;
        *(float4*)&f2e_s[idx] = *(const float4*)(g_f2e + base + idx);
    }

    // prologue: issue group chunks k=0,1 (global ch = 3k+wg)
#pragma unroll
    for (int p = 0; p < 2; p++) {
        const int ch = 3 * p + wg;
        const uint32_t aslot = agb + p * SLOT_A;
        const uint32_t bslot = bgb + p * SLOT_B;
#pragma unroll
        for (int q = 0; q < 4; q++) {
            const int row = arow + q * 32;
            CP_ASYNC16(aslot + a_woff + q * 32 * 144,
                       adjb + (size_t)row * N_ + ch * CH + acol);
        }
        CP_ASYNC16(bslot + b_woff,
                   whh + (size_t)(ch * CH + (wtid >> 3)) * 32 + (wtid & 7) * 4);
        CP_COMMIT();
    }
    __syncthreads();   // f2 table visible to all groups

    const float f1e_lo = g_f1e[base + i0 + r_lo];
    const float f1e_hi = g_f1e[base + i0 + r_hi];
    float dlo = 0.f, dhi = 0.f;

    float c[8][4];
#pragma unroll
    for (int nt = 0; nt < 8; nt++)
#pragma unroll
        for (int q = 0; q < 4; q++) c[nt][q] = 0.f;

    const uint32_t bar_id = wg + 1;

    for (int k = 0; k < glen; k++) {
        CP_WAIT1();          // this group's chunk k complete (k+1 may fly)
        GBAR(bar_id);        // publish chunk k; seal WAR on slot (k+2)%3

        // issue chunk k+2 (global ch = 3(k+2)+wg)
        if (k + 2 < glen) {
            const int ch = 3 * (k + 2) + wg;
            const uint32_t aslot = agb + ((k + 2) % 3) * SLOT_A;
            const uint32_t bslot = bgb + ((k + 2) % 3) * SLOT_B;
#pragma unroll
            for (int q = 0; q < 4; q++) {
                const int row = arow + q * 32;
                CP_ASYNC16(aslot + a_woff + q * 32 * 144,
                           adjb + (size_t)row * N_ + ch * CH + acol);
            }
            CP_ASYNC16(bslot + b_woff,
                       whh + (size_t)(ch * CH + (wtid >> 3)) * 32 + (wtid & 7) * 4);
        }
        CP_COMMIT();         // keep group counter aligned

        const uint32_t adjslot = agb + (k % 3) * SLOT_A;
        const uint32_t bslot   = bgb + (k % 3) * SLOT_B;
        const int jb0 = (3 * k + wg) * CH;

        // stage1: attention-weight A-fragments (fp32 math, one fp16 rounding)
        uint32_t ah[2][4];
#pragma unroll
        for (int s = 0; s < 2; s++) {
            const int co = s * 64 + tg * 8;
            int2 alo0, alo8, ahi0, ahi8;
            lds64(alo0, adjslot + r_lo * 144 + co);
            lds64(alo8, adjslot + r_lo * 144 + co + 32);
            lds64(ahi0, adjslot + r_hi * 144 + co);
            lds64(ahi8, adjslot + r_hi * 144 + co + 32);

            const int jb = jb0 + s * 16 + 2 * tg;
            const float2 e01 = *(const float2*)&f2e_s[jb];
            const float2 e89 = *(const float2*)&f2e_s[jb + 8];

            float fe;
            fe = f1e_lo + e01.x;
            float wl0 = (alo0.x > 0) ? ex2(fmaxf(fe, 0.2f * fe)) : 0.f;
            fe = f1e_lo + e01.y;
            float wl1 = (alo0.y > 0) ? ex2(fmaxf(fe, 0.2f * fe)) : 0.f;
            fe = f1e_lo + e89.x;
            float wl8 = (alo8.x > 0) ? ex2(fmaxf(fe, 0.2f * fe)) : 0.f;
            fe = f1e_lo + e89.y;
            float wl9 = (alo8.y > 0) ? ex2(fmaxf(fe, 0.2f * fe)) : 0.f;
            fe = f1e_hi + e01.x;
            float wh0 = (ahi0.x > 0) ? ex2(fmaxf(fe, 0.2f * fe)) : 0.f;
            fe = f1e_hi + e01.y;
            float wh1 = (ahi0.y > 0) ? ex2(fmaxf(fe, 0.2f * fe)) : 0.f;
            fe = f1e_hi + e89.x;
            float wh8 = (ahi8.x > 0) ? ex2(fmaxf(fe, 0.2f * fe)) : 0.f;
            fe = f1e_hi + e89.y;
            float wh9 = (ahi8.y > 0) ? ex2(fmaxf(fe, 0.2f * fe)) : 0.f;

            dlo += (wl0 + wl1) + (wl8 + wl9);
            dhi += (wh0 + wh1) + (wh8 + wh9);

            ah[s][0] = pack2h(wl0, wl1);
            ah[s][1] = pack2h(wh0, wh1);
            ah[s][2] = pack2h(wl8, wl9);
            ah[s][3] = pack2h(wh8, wh9);
        }

        // ldmatrix B fragments + 16 mma per chunk
        const uint32_t b_rd = bslot + (lane & 15) * 144 + ((lane >> 4) << 4);
#pragma unroll
        for (int s = 0; s < 2; s++) {
#pragma unroll
            for (int n16 = 0; n16 < 4; n16++) {
                uint32_t b0, b1, b2, b3;
                ldsm4t(b0, b1, b2, b3, b_rd + s * 16 * 144 + n16 * 32);
                mma16816(c[n16 * 2],     ah[s], b0, b1);
                mma16816(c[n16 * 2 + 1], ah[s], b2, b3);
            }
        }
    }

    // ---- merge the three groups' partials ----
    dlo += __shfl_xor_sync(0xffffffffu, dlo, 1);
    dlo += __shfl_xor_sync(0xffffffffu, dlo, 2);
    dhi += __shfl_xor_sync(0xffffffffu, dhi, 1);
    dhi += __shfl_xor_sync(0xffffffffu, dhi, 2);

    CP_WAIT0();
    __syncthreads();   // all pipelines done; SMEM rings reusable

    float* cbuf1 = (float*)sm;                    // group1: 128x64 f32 = 32KB
    float* cbuf2 = (float*)(sm + 32768);          // group2: 32KB
    float* dbuf1 = (float*)(sm + 65536);          // 128 floats
    float* dbuf2 = (float*)(sm + 66560);          // 128 floats

    if (wg > 0) {
        float* cb = (wg == 1) ? cbuf1 : cbuf2;
        float* db = (wg == 1) ? dbuf1 : dbuf2;
#pragma unroll
        for (int nt = 0; nt < 8; nt++) {
            const int col = nt * 8 + 2 * tg;
            cb[r_lo * 64 + col]     = c[nt][0];
            cb[r_lo * 64 + col + 1] = c[nt][1];
            cb[r_hi * 64 + col]     = c[nt][2];
            cb[r_hi * 64 + col + 1] = c[nt][3];
        }
        if (tg == 0) {
            db[r_lo] = dlo;
            db[r_hi] = dhi;
        }
    }
    __syncthreads();

    if (wg == 0) {
        const float rlo = __fdividef(1.f, dlo + dbuf1[r_lo] + dbuf2[r_lo]);
        const float rhi = __fdividef(1.f, dhi + dbuf1[r_hi] + dbuf2[r_hi]);
        float* olo = out + (size_t)(base + i0 + r_lo) * HID;
        float* ohi = out + (size_t)(base + i0 + r_hi) * HID;
#pragma unroll
        for (int nt = 0; nt < 8; nt++) {
            const int col = nt * 8 + 2 * tg;
            *(float2*)&olo[col] = make_float2(
                (c[nt][0] + cbuf1[r_lo * 64 + col] + cbuf2[r_lo * 64 + col]) * rlo,
                (c[nt][1] + cbuf1[r_lo * 64 + col + 1] + cbuf2[r_lo * 64 + col + 1]) * rlo);
            *(float2*)&ohi[col] = make_float2(
                (c[nt][2] + cbuf1[r_hi * 64 + col] + cbuf2[r_hi * 64 + col]) * rhi,
                (c[nt][3] + cbuf1[r_hi * 64 + col + 1] + cbuf2[r_hi * 64 + col + 1]) * rhi);
        }
    }
}

// ---------------------------------------------------------------------------
extern "C" void kernel_launch(void* const* d_in, const int* in_sizes, int n_in,
                              void* d_out, int out_size) {
    const float* X  = (const float*)d_in[0];   // node_features [8,2048,256]
    const int*   A  = (const int*)d_in[1];     // adj [8,2048,2048]
    const float* W  = (const float*)d_in[2];   // W [256,64]
    const float* av = (const float*)d_in[3];   // a [128,1]
    float* out = (float*)d_out;                // [8,2048,64] f32

    cudaFuncSetAttribute(gemm_wh, cudaFuncAttributeMaxDynamicSharedMemorySize,
                         SMEM_GW);
    cudaFuncSetAttribute(gat_main, cudaFuncAttributeMaxDynamicSharedMemorySize,
                         SMEM_DYN);

    gemm_wh<<<(B_ * N_) / 128, 256, SMEM_GW>>>(X, W, av);
    gat_main<<<dim3(B_ * (N_ / TI)), 768, SMEM_DYN>>>(A, out);
}

// round 17
// speedup vs baseline: 1.4771x; 1.4771x over previous
#include <cuda_runtime.h>
#include <cuda_fp16.h>
#include <cstdint>

#define B_   8
#define N_   2048
#define DIN  256
#define HID  64
#define TI   128
#define CH   32
#define NCH  (N_ / CH)
#define KPG  (NCH / 2)        // chunks per warpgroup (32)
#define L2E  1.4426950408889634f

// ---- gat_main dynamic SMEM (R12 layout + E2/F2 tables) ----
#define SLOT_A  (128 * 144)                 // adj tile: 128 rows x 32 ints, 144B-padded
#define ABYTES  (8 * SLOT_A)                // 2 groups x 4 slots = 147456
#define SLOT_B  (32 * 144)                  // B tile: 32 nodes x 64 fp16, 144B-padded
#define BOFF    ABYTES
#define BBYTES  (8 * SLOT_B)                // 36864
#define F2EOFF  (BOFF + BBYTES)             // 184320
#define E2OFF   (F2EOFF + N_ * 4)           // 192512
#define F2OFF   (E2OFF + N_ * 4)            // 200704
#define SMEM_DYN (F2OFF + N_ * 4)           // 208896

// ---- gemm_wh dynamic SMEM (R12-proven) ----
#define GW_WOFF  0                          // W fp16 [256][72]  = 36864
#define GW_XOFF  36864                      // X ring: 4 slots x (128 x 144B)
#define GW_XSLOT 18432
#define SMEM_GW  (GW_XOFF + 4 * GW_XSLOT)   // 110592

// Scratch (device globals — no allocation allowed)
__device__ uint32_t g_Whh[B_ * N_ * HID / 2];       // fp16x2 Wh  [node][h/2]
__device__ float g_f1e[B_ * N_];                    // f1*log2e (sign threshold)
__device__ float g_E1[B_ * N_], g_F1[B_ * N_];      // 2^f1e, 2^(0.2 f1e)
__device__ float g_f2e[B_ * N_];                    // f2*log2e
__device__ float g_E2[B_ * N_], g_F2[B_ * N_];      // 2^f2e, 2^(0.2 f2e)

// ---------------- helpers ----------------
static __device__ __forceinline__ uint32_t smem_u32(const void* p) {
    uint32_t a;
    asm("{ .reg .u64 t; cvta.to.shared.u64 t, %1; cvt.u32.u64 %0, t; }"
        : "=r"(a) : "l"(p));
    return a;
}
static __device__ __forceinline__ float ex2(float x) {
    float y;
    asm("ex2.approx.f32 %0, %1;" : "=f"(y) : "f"(x));
    return y;
}
static __device__ __forceinline__ uint32_t pack2h(float w0, float w1) {
    uint32_t r;
    asm("cvt.rn.f16x2.f32 %0, %1, %2;" : "=r"(r) : "f"(w1), "f"(w0));
    return r;
}
// split pair into fp16 hi + fp16 lo (exact residual, ~2^-22 rel)
static __device__ __forceinline__ void split2h(float w0, float w1,
                                               uint32_t& hi, uint32_t& lo) {
    uint32_t h = pack2h(w0, w1);
    float h0, h1;
    asm("{ .reg .f16 a,b; mov.b32 {a,b}, %2; cvt.f32.f16 %0, a; cvt.f32.f16 %1, b; }"
        : "=f"(h0), "=f"(h1) : "r"(h));
    lo = pack2h(w0 - h0, w1 - h1);
    hi = h;
}
static __device__ __forceinline__ void ldsm4t(uint32_t& r0, uint32_t& r1,
                                              uint32_t& r2, uint32_t& r3,
                                              uint32_t a) {
    asm volatile("ldmatrix.sync.aligned.m8n8.x4.trans.shared.b16 {%0,%1,%2,%3}, [%4];"
                 : "=r"(r0), "=r"(r1), "=r"(r2), "=r"(r3) : "r"(a));
}
static __device__ __forceinline__ void lds64(int2& v, uint32_t a) {
    asm volatile("ld.shared.v2.u32 {%0,%1}, [%2];" : "=r"(v.x), "=r"(v.y) : "r"(a));
}
static __device__ __forceinline__ void lds64f(float2& v, uint32_t a) {
    asm volatile("ld.shared.v2.f32 {%0,%1}, [%2];" : "=f"(v.x), "=f"(v.y) : "r"(a));
}
static __device__ __forceinline__ void mma16816(float* c, const uint32_t* a,
                                                uint32_t b0, uint32_t b1) {
    asm volatile(
        "mma.sync.aligned.m16n8k16.row.col.f32.f16.f16.f32 "
        "{%0,%1,%2,%3}, {%4,%5,%6,%7}, {%8,%9}, {%0,%1,%2,%3};"
        : "+f"(c[0]), "+f"(c[1]), "+f"(c[2]), "+f"(c[3])
        : "r"(a[0]), "r"(a[1]), "r"(a[2]), "r"(a[3]), "r"(b0), "r"(b1));
}
#define CP_ASYNC16(dst, src) \
    asm volatile("cp.async.cg.shared.global [%0], [%1], 16;" :: "r"(dst), "l"(src) : "memory")
#define CP_COMMIT()  asm volatile("cp.async.commit_group;" ::: "memory")
#define CP_WAIT2()   asm volatile("cp.async.wait_group 2;" ::: "memory")
#define CP_WAIT0()   asm volatile("cp.async.wait_group 0;" ::: "memory")
#define GBAR(id)     asm volatile("bar.sync %0, 256;" :: "r"(id) : "memory")

// masked factorized weight: (adj>0) ? (pos ? E1*E2j : F1*F2j) : 0
static __device__ __forceinline__ float wsel(int adjv, float f2e, float thr,
                                             float E1, float F1,
                                             float E2j, float F2j) {
    const bool p = f2e > thr;
    float t = p ? E1 : F1;
    t = (adjv > 0) ? t : 0.f;
    return t * (p ? E2j : F2j);
}

// ---------------------------------------------------------------------------
// Kernel A (R12-proven): Wh = X @ W via mma.sync fp16 2-term split; epilogue
// emits packed fp16x2 Wh and the factorized exponential tables
// (f1e threshold, E1/F1 per node; f2e, E2/F2 per node).
// ---------------------------------------------------------------------------
__global__ __launch_bounds__(256) void gemm_wh(const float* __restrict__ X,
                                               const float* __restrict__ W,
                                               const float* __restrict__ a) {
    extern __shared__ __align__(16) char smw[];
    const uint32_t smb = smem_u32(smw);
    const uint32_t wsb = smb + GW_WOFF;
    const uint32_t xsb = smb + GW_XOFF;

    const int tid = threadIdx.x;
    const int lane = tid & 31, w8 = tid >> 5;
    const int g = lane >> 2, tg = lane & 3;
    const int r0 = blockIdx.x * 128;

    // convert W (fp32 global) -> fp16 SMEM [256][72-halves rows = 144B]
#pragma unroll
    for (int i = 0; i < 16; i++) {
        const int e = (i * 256 + tid) * 4;
        const int k = e >> 6, n = e & 63;
        const float4 wv = *(const float4*)(W + e);
        *(uint32_t*)(smw + GW_WOFF + k * 144 + n * 2)     = pack2h(wv.x, wv.y);
        *(uint32_t*)(smw + GW_WOFF + k * 144 + n * 2 + 4) = pack2h(wv.z, wv.w);
    }

    const int xrow = tid >> 1;
    const uint32_t xdst = xsb + xrow * 144 + (tid & 1) * 64;
    const float* xsrc = X + (size_t)(r0 + xrow) * DIN + (tid & 1) * 16;

#pragma unroll
    for (int p = 0; p < 3; p++) {
#pragma unroll
        for (int q = 0; q < 4; q++)
            CP_ASYNC16(xdst + p * GW_XSLOT + q * 16, xsrc + p * 32 + q * 4);
        CP_COMMIT();
    }

    float c[8][4];
#pragma unroll
    for (int nt = 0; nt < 8; nt++)
#pragma unroll
        for (int q = 0; q < 4; q++) c[nt][q] = 0.f;

    for (int kc = 0; kc < 8; kc++) {
        CP_WAIT2();
        __syncthreads();
        if (kc + 3 < 8) {
#pragma unroll
            for (int q = 0; q < 4; q++)
                CP_ASYNC16(xdst + ((kc + 3) & 3) * GW_XSLOT + q * 16,
                           xsrc + (kc + 3) * 32 + q * 4);
        }
        CP_COMMIT();

        const uint32_t xslot = xsb + (kc & 3) * GW_XSLOT;
#pragma unroll
        for (int s = 0; s < 2; s++) {
            const uint32_t abase = xslot + (w8 * 16 + g) * 144 + (s * 16 + 2 * tg) * 4;
            float2 x0, x1, x2, x3;
            lds64f(x0, abase);
            lds64f(x1, abase + 8 * 144);
            lds64f(x2, abase + 32);
            lds64f(x3, abase + 8 * 144 + 32);
            uint32_t ahi[4], alo[4];
            split2h(x0.x, x0.y, ahi[0], alo[0]);
            split2h(x1.x, x1.y, ahi[1], alo[1]);
            split2h(x2.x, x2.y, ahi[2], alo[2]);
            split2h(x3.x, x3.y, ahi[3], alo[3]);

            const uint32_t brd = wsb + (kc * 32 + s * 16 + (lane & 15)) * 144 +
                                 ((lane >> 4) << 4);
#pragma unroll
            for (int n16 = 0; n16 < 4; n16++) {
                uint32_t b0, b1, b2, b3;
                ldsm4t(b0, b1, b2, b3, brd + n16 * 32);
                mma16816(c[n16 * 2],     ahi, b0, b1);
                mma16816(c[n16 * 2],     alo, b0, b1);
                mma16816(c[n16 * 2 + 1], ahi, b2, b3);
                mma16816(c[n16 * 2 + 1], alo, b2, b3);
            }
        }
    }

    const int r_lo = w8 * 16 + g, r_hi = r_lo + 8;
    float p1lo = 0.f, p2lo = 0.f, p1hi = 0.f, p2hi = 0.f;
#pragma unroll
    for (int nt = 0; nt < 8; nt++) {
        const int col = nt * 8 + 2 * tg;
        const float a1x = a[col], a1y = a[col + 1];
        const float a2x = a[HID + col], a2y = a[HID + col + 1];
        p1lo += c[nt][0] * a1x + c[nt][1] * a1y;
        p2lo += c[nt][0] * a2x + c[nt][1] * a2y;
        p1hi += c[nt][2] * a1x + c[nt][3] * a1y;
        p2hi += c[nt][2] * a2x + c[nt][3] * a2y;
        g_Whh[(size_t)(r0 + r_lo) * 32 + nt * 4 + tg] = pack2h(c[nt][0], c[nt][1]);
        g_Whh[(size_t)(r0 + r_hi) * 32 + nt * 4 + tg] = pack2h(c[nt][2], c[nt][3]);
    }
#pragma unroll
    for (int s = 1; s <= 2; s <<= 1) {
        p1lo += __shfl_xor_sync(0xffffffffu, p1lo, s);
        p2lo += __shfl_xor_sync(0xffffffffu, p2lo, s);
        p1hi += __shfl_xor_sync(0xffffffffu, p1hi, s);
        p2hi += __shfl_xor_sync(0xffffffffu, p2hi, s);
    }
    if (tg == 0) {
        const float f1lo = p1lo * L2E, f1hi = p1hi * L2E;
        const float f2lo = p2lo * L2E, f2hi = p2hi * L2E;
        g_f1e[r0 + r_lo] = f1lo;
        g_E1[r0 + r_lo]  = ex2(f1lo);
        g_F1[r0 + r_lo]  = ex2(0.2f * f1lo);
        g_f2e[r0 + r_lo] = f2lo;
        g_E2[r0 + r_lo]  = ex2(f2lo);
        g_F2[r0 + r_lo]  = ex2(0.2f * f2lo);
        g_f1e[r0 + r_hi] = f1hi;
        g_E1[r0 + r_hi]  = ex2(f1hi);
        g_F1[r0 + r_hi]  = ex2(0.2f * f1hi);
        g_f2e[r0 + r_hi] = f2hi;
        g_E2[r0 + r_hi]  = ex2(f2hi);
        g_F2[r0 + r_hi]  = ex2(0.2f * f2hi);
    }
}

// ---------------------------------------------------------------------------
// Main kernel: R12-exact topology (59.9us-verified). ONE change: stage1 uses
// the factorized exponential — w = (fe>0) ? E1i*E2j : F1i*F2j, masked —
// replacing the in-loop FADD/FMUL/FMAX/MUFU chain with all-fixed-pipe
// FSETP/FSEL/FMUL. Zero MUFU in the loop; E2/F2 tables join f2e in SMEM.
// ---------------------------------------------------------------------------
__global__ __launch_bounds__(512) void gat_main(const int* __restrict__ adj,
                                                float* __restrict__ out) {
    extern __shared__ __align__(16) char sm[];
    const uint32_t smb = smem_u32(sm);
    float* f2e_s = (float*)(sm + F2EOFF);
    float* E2_s  = (float*)(sm + E2OFF);
    float* F2_s  = (float*)(sm + F2OFF);

    const int tid = threadIdx.x;
    const int wg = tid >> 8;                 // warpgroup 0/1 (even/odd chunks)
    const int wtid = tid & 255;
    const int lane = tid & 31, w8 = wtid >> 5;   // warp-in-group 0..7
    const int g = lane >> 2, tg = lane & 3;
    const int b = blockIdx.x >> 4;
    const int i0 = (blockIdx.x & 15) * TI;
    const int base = b * N_;

    const int r_lo = w8 * 16 + g, r_hi = r_lo + 8;

    const int* adjb = adj + (size_t)b * N_ * N_ + (size_t)i0 * N_;
    const uint32_t* whh = g_Whh + (size_t)base * 32;

    // group-private ring bases
    const uint32_t agb = smb + wg * 4 * SLOT_A;
    const uint32_t bgb = smb + BOFF + wg * 4 * SLOT_B;

    // cp.async segment mapping (within group)
    const int arow = wtid >> 3, acol = (wtid & 7) * 4;
    const uint32_t a_woff = arow * 144 + acol * 4;           // +q*32*144
    const uint32_t b_woff = (wtid >> 3) * 144 + (wtid & 7) * 16;

    // stage f2e/E2/F2 tables (512 threads: one float4 each per table)
    {
        const int idx = tid * 4;
        *(float4*)&f2e_s[idx] = *(const float4*)(g_f2e + base + idx);
        *(float4*)&E2_s[idx]  = *(const float4*)(g_E2 + base + idx);
        *(float4*)&F2_s[idx]  = *(const float4*)(g_F2 + base + idx);
    }

    // prologue: each group issues its chunks k=0,1,2 (global ch = 2k+wg)
#pragma unroll
    for (int p = 0; p < 3; p++) {
        const int ch = 2 * p + wg;
        const uint32_t aslot = agb + p * SLOT_A;
        const uint32_t bslot = bgb + p * SLOT_B;
#pragma unroll
        for (int q = 0; q < 4; q++) {
            const int row = arow + q * 32;
            CP_ASYNC16(aslot + a_woff + q * 32 * 144,
                       adjb + (size_t)row * N_ + ch * CH + acol);
        }
        CP_ASYNC16(bslot + b_woff, whh + (size_t)(ch * CH + (wtid >> 3)) * 32 + (wtid & 7) * 4);
        CP_COMMIT();
    }
    __syncthreads();   // tables visible to both groups

    // per-row constants (factorized exponentials)
    const float thr_lo = -g_f1e[base + i0 + r_lo];
    const float thr_hi = -g_f1e[base + i0 + r_hi];
    const float E1lo = g_E1[base + i0 + r_lo], F1lo = g_F1[base + i0 + r_lo];
    const float E1hi = g_E1[base + i0 + r_hi], F1hi = g_F1[base + i0 + r_hi];
    float dlo = 0.f, dhi = 0.f;

    float c[8][4];
#pragma unroll
    for (int nt = 0; nt < 8; nt++)
#pragma unroll
        for (int q = 0; q < 4; q++) c[nt][q] = 0.f;

    const uint32_t bar_id = wg + 1;

    for (int k = 0; k < KPG; k++) {
        CP_WAIT2();          // this group's chunk k complete
        GBAR(bar_id);        // publish chunk k; seal WAR on slot (k+3)&3

        // issue chunk k+3 (global ch = 2(k+3)+wg)
        if (k + 3 < KPG) {
            const int ch = 2 * (k + 3) + wg;
            const uint32_t aslot = agb + ((k + 3) & 3) * SLOT_A;
            const uint32_t bslot = bgb + ((k + 3) & 3) * SLOT_B;
#pragma unroll
            for (int q = 0; q < 4; q++) {
                const int row = arow + q * 32;
                CP_ASYNC16(aslot + a_woff + q * 32 * 144,
                           adjb + (size_t)row * N_ + ch * CH + acol);
            }
            CP_ASYNC16(bslot + b_woff,
                       whh + (size_t)(ch * CH + (wtid >> 3)) * 32 + (wtid & 7) * 4);
        }
        CP_COMMIT();         // keep group counter aligned

        const uint32_t adjslot = agb + (k & 3) * SLOT_A;
        const uint32_t bslot   = bgb + (k & 3) * SLOT_B;
        const int jb0 = (2 * k + wg) * CH;

        // stage1: factorized attention weights (all fixed-pipe, no MUFU)
        uint32_t ah[2][4];
#pragma unroll
        for (int s = 0; s < 2; s++) {
            const int co = s * 64 + tg * 8;
            int2 alo0, alo8, ahi0, ahi8;
            lds64(alo0, adjslot + r_lo * 144 + co);
            lds64(alo8, adjslot + r_lo * 144 + co + 32);
            lds64(ahi0, adjslot + r_hi * 144 + co);
            lds64(ahi8, adjslot + r_hi * 144 + co + 32);

            const int jb = jb0 + s * 16 + 2 * tg;
            const float2 e01 = *(const float2*)&f2e_s[jb];
            const float2 e89 = *(const float2*)&f2e_s[jb + 8];
            const float2 E01 = *(const float2*)&E2_s[jb];
            const float2 E89 = *(const float2*)&E2_s[jb + 8];
            const float2 F01 = *(const float2*)&F2_s[jb];
            const float2 F89 = *(const float2*)&F2_s[jb + 8];

            const float wl0 = wsel(alo0.x, e01.x, thr_lo, E1lo, F1lo, E01.x, F01.x);
            const float wl1 = wsel(alo0.y, e01.y, thr_lo, E1lo, F1lo, E01.y, F01.y);
            const float wl8 = wsel(alo8.x, e89.x, thr_lo, E1lo, F1lo, E89.x, F89.x);
            const float wl9 = wsel(alo8.y, e89.y, thr_lo, E1lo, F1lo, E89.y, F89.y);
            const float wh0 = wsel(ahi0.x, e01.x, thr_hi, E1hi, F1hi, E01.x, F01.x);
            const float wh1 = wsel(ahi0.y, e01.y, thr_hi, E1hi, F1hi, E01.y, F01.y);
            const float wh8 = wsel(ahi8.x, e89.x, thr_hi, E1hi, F1hi, E89.x, F89.x);
            const float wh9 = wsel(ahi8.y, e89.y, thr_hi, E1hi, F1hi, E89.y, F89.y);

            dlo += (wl0 + wl1) + (wl8 + wl9);
            dhi += (wh0 + wh1) + (wh8 + wh9);

            ah[s][0] = pack2h(wl0, wl1);
            ah[s][1] = pack2h(wh0, wh1);
            ah[s][2] = pack2h(wl8, wl9);
            ah[s][3] = pack2h(wh8, wh9);
        }

        // ldmatrix B fragments + 16 mma per chunk
        const uint32_t b_rd = bslot + (lane & 15) * 144 + ((lane >> 4) << 4);
#pragma unroll
        for (int s = 0; s < 2; s++) {
#pragma unroll
            for (int n16 = 0; n16 < 4; n16++) {
                uint32_t b0, b1, b2, b3;
                ldsm4t(b0, b1, b2, b3, b_rd + s * 16 * 144 + n16 * 32);
                mma16816(c[n16 * 2],     ah[s], b0, b1);
                mma16816(c[n16 * 2 + 1], ah[s], b2, b3);
            }
        }
    }

    // ---- merge the two groups' partials ----
    dlo += __shfl_xor_sync(0xffffffffu, dlo, 1);
    dlo += __shfl_xor_sync(0xffffffffu, dlo, 2);
    dhi += __shfl_xor_sync(0xffffffffu, dhi, 1);
    dhi += __shfl_xor_sync(0xffffffffu, dhi, 2);

    CP_WAIT0();
    __syncthreads();   // both pipelines done; SMEM reusable

    float* cbuf = (float*)sm;                   // 128 x 64 fp32 = 32KB
    float* dbuf = (float*)(sm + 32768);         // 128 floats

    if (wg == 1) {
#pragma unroll
        for (int nt = 0; nt < 8; nt++) {
            const int col = nt * 8 + 2 * tg;
            cbuf[r_lo * 64 + col]     = c[nt][0];
            cbuf[r_lo * 64 + col + 1] = c[nt][1];
            cbuf[r_hi * 64 + col]     = c[nt][2];
            cbuf[r_hi * 64 + col + 1] = c[nt][3];
        }
        if (tg == 0) {
            dbuf[r_lo] = dlo;
            dbuf[r_hi] = dhi;
        }
    }
    __syncthreads();

    if (wg == 0) {
        const float rlo = __fdividef(1.f, dlo + dbuf[r_lo]);
        const float rhi = __fdividef(1.f, dhi + dbuf[r_hi]);
        float* olo = out + (size_t)(base + i0 + r_lo) * HID;
        float* ohi = out + (size_t)(base + i0 + r_hi) * HID;
#pragma unroll
        for (int nt = 0; nt < 8; nt++) {
            const int col = nt * 8 + 2 * tg;
            *(float2*)&olo[col] = make_float2((c[nt][0] + cbuf[r_lo * 64 + col]) * rlo,
                                              (c[nt][1] + cbuf[r_lo * 64 + col + 1]) * rlo);
            *(float2*)&ohi[col] = make_float2((c[nt][2] + cbuf[r_hi * 64 + col]) * rhi,
                                              (c[nt][3] + cbuf[r_hi * 64 + col + 1]) * rhi);
        }
    }
}

// ---------------------------------------------------------------------------
extern "C" void kernel_launch(void* const* d_in, const int* in_sizes, int n_in,
                              void* d_out, int out_size) {
    const float* X  = (const float*)d_in[0];   // node_features [8,2048,256]
    const int*   A  = (const int*)d_in[1];     // adj [8,2048,2048]
    const float* W  = (const float*)d_in[2];   // W [256,64]
    const float* av = (const float*)d_in[3];   // a [128,1]
    float* out = (float*)d_out;                // [8,2048,64] f32

    cudaFuncSetAttribute(gemm_wh, cudaFuncAttributeMaxDynamicSharedMemorySize,
                         SMEM_GW);
    cudaFuncSetAttribute(gat_main, cudaFuncAttributeMaxDynamicSharedMemorySize,
                         SMEM_DYN);

    gemm_wh<<<(B_ * N_) / 128, 256, SMEM_GW>>>(X, W, av);
    gat_main<<<dim3(B_ * (N_ / TI)), 512, SMEM_DYN>>>(A, out);
}